// round 5
// baseline (speedup 1.0000x reference)
#include <cuda_runtime.h>
#include <math.h>

// Shapes fixed by the problem
#define BATCH 8
#define CCH   1024
#define LL    4096
#define NPB   (CCH*LL)            // 4,194,304 elements per batch
#define TL    8                   // L-tile per block in main kernel
#define SSTR  9                   // smem row stride (9 coprime 32 -> conflict-free column sweeps)
#define K3_THREADS 256
#define K3_BLOCKS  (BATCH*(LL/TL))   // 4096
#define SMEMB (2u*CCH*SSTR*sizeof(float))  // 73,728 bytes

// Scratch (no allocations allowed)
__device__ double g_bsum[BATCH];
__device__ double g_bsumsq[BATCH];
__device__ double g_loss;
__device__ float  g_margin[BATCH];

// ---------------------------------------------------------------------------
// K0: zero accumulators (graph replay safe)
// ---------------------------------------------------------------------------
__global__ void k_zero() {
  int t = threadIdx.x;
  if (t < BATCH) { g_bsum[t] = 0.0; g_bsumsq[t] = 0.0; }
  if (t == 0) g_loss = 0.0;
}

// ---------------------------------------------------------------------------
// K1: per-batch sum / sumsq of x_st (target). 256 blocks per batch.
// ---------------------------------------------------------------------------
__global__ void __launch_bounds__(256) k_stats(const float* __restrict__ xt) {
  int b = blockIdx.x >> 8;
  int chunk = blockIdx.x & 255;
  const float4* p = reinterpret_cast<const float4*>(xt)
                    + (size_t)b * (NPB/4) + (size_t)chunk * 4096;
  int tid = threadIdx.x;
  float s = 0.f, s2 = 0.f;
#pragma unroll
  for (int k = 0; k < 16; k++) {
    float4 v = p[tid + k*256];
    s  += (v.x + v.y) + (v.z + v.w);
    s2 += (v.x*v.x + v.y*v.y) + (v.z*v.z + v.w*v.w);
  }
#pragma unroll
  for (int o = 16; o; o >>= 1) {
    s  += __shfl_xor_sync(0xffffffffu, s,  o);
    s2 += __shfl_xor_sync(0xffffffffu, s2, o);
  }
  __shared__ float ws[8], ws2[8];
  int warp = tid >> 5, lane = tid & 31;
  if (lane == 0) { ws[warp] = s; ws2[warp] = s2; }
  __syncthreads();
  if (tid == 0) {
    float ts = 0.f, ts2 = 0.f;
#pragma unroll
    for (int w = 0; w < 8; w++) { ts += ws[w]; ts2 += ws2[w]; }
    atomicAdd(&g_bsum[b],   (double)ts);
    atomicAdd(&g_bsumsq[b], (double)ts2);
  }
}

// ---------------------------------------------------------------------------
// K2: margin finalize (8 scalars, double precision)
// ---------------------------------------------------------------------------
__global__ void k_margin() {
  int b = threadIdx.x;
  if (b >= BATCH) return;
  const double N = (double)NPB;
  double s = g_bsum[b], s2 = g_bsumsq[b];
  double mean = s / N;
  double var  = (s2 - s*s/N) / (N - 1.0);   // unbiased (ddof=1)
  double sd   = sqrt(fabs(var));
  double z    = -mean / sd;
  double cdf  = 0.5 * (1.0 + erf(z * 0.70710678118654752440));
  double safe = fmax(cdf, 1e-30);
  double ma   = -sd * exp(-(mean/sd)*(mean/sd)*0.5)
                / 2.50662827463100050241 / safe + mean;
  double m    = (cdf > 0.001) ? ma : (-3.0 * sd);
  g_margin[b] = (float)m;
}

// ---------------------------------------------------------------------------
// K3: main fused kernel. Each block: one batch b, 8 consecutive l columns,
// full C=1024 cached in SMEM for both tensors. Warp w owns column l=w.
// ---------------------------------------------------------------------------
__global__ void __launch_bounds__(K3_THREADS) k_main(
    const float* __restrict__ xs,   // x_ts (source)
    const float* __restrict__ xt,   // x_st (target)
    float* __restrict__ eout)       // entropy output base (d_out + 1)
{
  extern __shared__ float smem[];
  float* ss = smem;                 // [CCH * SSTR]
  float* st = smem + CCH * SSTR;    // [CCH * SSTR]
  __shared__ float wacc[8];

  int b  = blockIdx.x / (LL / TL);
  int l0 = (blockIdx.x % (LL / TL)) * TL;
  int tid = threadIdx.x;
  size_t base = (size_t)b * NPB + (size_t)l0;

  const float4* xs4 = reinterpret_cast<const float4*>(xs + base);
  const float4* xt4 = reinterpret_cast<const float4*>(xt + base);

  // Load both tiles: 1024 rows x 8 floats (2 float4 per row) per tensor.
#pragma unroll
  for (int k = 0; k < 8; k++) {
    int idx = tid + k * 256;
    int c = idx >> 1, q = idx & 1;
    float4 v = xs4[(size_t)c * (LL/4) + q];
    float4 w = xt4[(size_t)c * (LL/4) + q];
    float* d0 = ss + c * SSTR + q * 4;
    d0[0] = v.x; d0[1] = v.y; d0[2] = v.z; d0[3] = v.w;
    float* d1 = st + c * SSTR + q * 4;
    d1[0] = w.x; d1[1] = w.y; d1[2] = w.z; d1[3] = w.w;
  }
  __syncthreads();

  int warp = tid >> 5, lane = tid & 31;
  float margin = g_margin[b];
  const float* ps = ss + warp;   // column l = warp
  const float* pt = st + warp;

  // Sweep 1: maxes over C
  float ms = -1e30f, mt0 = -1e30f;
#pragma unroll 8
  for (int k = 0; k < 32; k++) {
    int off = (lane + 32*k) * SSTR;
    ms  = fmaxf(ms,  ps[off]);
    mt0 = fmaxf(mt0, pt[off]);
  }
#pragma unroll
  for (int o = 16; o; o >>= 1) {
    ms  = fmaxf(ms,  __shfl_xor_sync(0xffffffffu, ms,  o));
    mt0 = fmaxf(mt0, __shfl_xor_sync(0xffffffffu, mt0, o));
  }
  float mt = fmaxf(mt0, margin);   // max over C of target = max(max xt, margin)

  // Sweep 2: partition functions
  float zs = 0.f, zt = 0.f;
#pragma unroll 8
  for (int k = 0; k < 32; k++) {
    int off = (lane + 32*k) * SSTR;
    zs += __expf(ps[off] - ms);
    zt += __expf(fmaxf(pt[off], margin) - mt);
  }
#pragma unroll
  for (int o = 16; o; o >>= 1) {
    zs += __shfl_xor_sync(0xffffffffu, zs, o);
    zt += __shfl_xor_sync(0xffffffffu, zt, o);
  }
  float invzs = __fdividef(1.f, zs);
  float lzt   = __logf(zt);

  // Sweep 3: entropy = softmax(xs) * log_softmax(target); write back into ss
  float acc = 0.f;
  float* pso = ss + warp;
#pragma unroll 8
  for (int k = 0; k < 32; k++) {
    int off = (lane + 32*k) * SSTR;
    float p  = __expf(ps[off] - ms) * invzs;
    float lq = fmaxf(pt[off], margin) - mt - lzt;
    float e  = p * lq;
    pso[off] = e;
    acc += e;
  }
#pragma unroll
  for (int o = 16; o; o >>= 1) acc += __shfl_xor_sync(0xffffffffu, acc, o);
  if (lane == 0) wacc[warp] = acc;
  __syncthreads();
  if (tid == 0) {
    float t = 0.f;
#pragma unroll
    for (int w = 0; w < 8; w++) t += wacc[w];
    atomicAdd(&g_loss, (double)t);
  }

  // Write-out (coalesced; scalar 4B stores because eout = d_out+1 is 4B-aligned only)
  float* outb = eout + base;
#pragma unroll
  for (int k = 0; k < 8; k++) {
    int idx = tid + k * 256;
    int c = idx >> 1, q = idx & 1;
    const float* srcp = ss + c * SSTR + q * 4;
    float* dst = outb + (size_t)c * LL + q * 4;
    dst[0] = srcp[0]; dst[1] = srcp[1]; dst[2] = srcp[2]; dst[3] = srcp[3];
  }
}

// ---------------------------------------------------------------------------
// K4: loss = mean over B of mean over L of (-sum over C) = -total / (B*L)
// ---------------------------------------------------------------------------
__global__ void k_loss(float* __restrict__ out0) {
  if (threadIdx.x == 0) out0[0] = (float)(-g_loss / (double)(BATCH * LL));
}

// ---------------------------------------------------------------------------
extern "C" void kernel_launch(void* const* d_in, const int* in_sizes, int n_in,
                              void* d_out, int out_size) {
  // metadata order: x_s, x_t, x_ts, x_st, i
  const float* xs = (const float*)d_in[2];  // x_ts -> source
  const float* xt = (const float*)d_in[3];  // x_st -> target (margin source)
  float* out = (float*)d_out;               // [0] = loss, [1..] = entropy [B,C,L]

  cudaFuncSetAttribute(k_main, cudaFuncAttributeMaxDynamicSharedMemorySize,
                       (int)SMEMB);

  k_zero  <<<1, 32>>>();
  k_stats <<<BATCH * 256, 256>>>(xt);
  k_margin<<<1, 32>>>();
  k_main  <<<K3_BLOCKS, K3_THREADS, SMEMB>>>(xs, xt, out + 1);
  k_loss  <<<1, 32>>>(out);
}

// round 8
// speedup vs baseline: 1.8630x; 1.8630x over previous
#include <cuda_runtime.h>
#include <math.h>

// Shapes fixed by the problem
#define BATCH 8
#define CCH   1024
#define LL    4096
#define NPB   (CCH*LL)            // 4,194,304 elements per batch
#define NBL   (BATCH*LL)          // 32,768 (b,l) pairs

// Scratch (no allocations allowed)
__device__ double g_bsum[BATCH];
__device__ double g_bsumsq[BATCH];
__device__ double g_loss;
__device__ float  g_margin[BATCH];
__device__ __align__(16) float g_zs[NBL];   // later: 1/zs
__device__ __align__(16) float g_zt[NBL];   // later: log zt

// ---------------------------------------------------------------------------
// K0: zero all accumulators (graph replay safe). 128 blocks x 256.
// ---------------------------------------------------------------------------
__global__ void __launch_bounds__(256) k_zero() {
  int i = blockIdx.x * 256 + threadIdx.x;   // 0..32767
  g_zs[i] = 0.f;
  g_zt[i] = 0.f;
  if (i < BATCH) { g_bsum[i] = 0.0; g_bsumsq[i] = 0.0; }
  if (i == 0) g_loss = 0.0;
}

// ---------------------------------------------------------------------------
// K_A: fused pass over xs and xt.
//   - zs[b,l] += sum_c exp(xs[b,c,l])        (no max subtraction; safe in fp32)
//   - per-batch sum / sumsq of xt            (for margin)
// Grid: 512 blocks = 8 b x 4 l-tiles(1024) x 16 c-chunks(64). Block 256 thr,
// each thread owns 4 consecutive l (float4), loops 64 c's. Fully coalesced.
// ---------------------------------------------------------------------------
__global__ void __launch_bounds__(256) k_A(const float* __restrict__ xs,
                                           const float* __restrict__ xt) {
  int bid = blockIdx.x;
  int cc = bid & 15;
  int lt = (bid >> 4) & 3;
  int b  = bid >> 6;
  int t  = threadIdx.x;
  int l  = lt * 1024 + t * 4;

  size_t base = (size_t)b * NPB + (size_t)(cc * 64) * LL + l;
  const float4* ps = reinterpret_cast<const float4*>(xs + base);
  const float4* pt = reinterpret_cast<const float4*>(xt + base);

  float z0 = 0.f, z1 = 0.f, z2 = 0.f, z3 = 0.f;
  float s = 0.f, s2 = 0.f;
#pragma unroll 4
  for (int c = 0; c < 64; c++) {
    float4 a = ps[(size_t)c * (LL/4)];
    float4 w = pt[(size_t)c * (LL/4)];
    z0 += __expf(a.x); z1 += __expf(a.y);
    z2 += __expf(a.z); z3 += __expf(a.w);
    s  += (w.x + w.y) + (w.z + w.w);
    s2 += (w.x*w.x + w.y*w.y) + (w.z*w.z + w.w*w.w);
  }

  float* zp = &g_zs[b * LL + l];
  atomicAdd(zp + 0, z0); atomicAdd(zp + 1, z1);
  atomicAdd(zp + 2, z2); atomicAdd(zp + 3, z3);

  // block reduce stats -> double atomics
#pragma unroll
  for (int o = 16; o; o >>= 1) {
    s  += __shfl_xor_sync(0xffffffffu, s,  o);
    s2 += __shfl_xor_sync(0xffffffffu, s2, o);
  }
  __shared__ float ws[8], ws2[8];
  int warp = t >> 5, lane = t & 31;
  if (lane == 0) { ws[warp] = s; ws2[warp] = s2; }
  __syncthreads();
  if (t == 0) {
    float ts = 0.f, ts2 = 0.f;
#pragma unroll
    for (int w = 0; w < 8; w++) { ts += ws[w]; ts2 += ws2[w]; }
    atomicAdd(&g_bsum[b],   (double)ts);
    atomicAdd(&g_bsumsq[b], (double)ts2);
  }
}

// ---------------------------------------------------------------------------
// K_margin: finalize margin per batch (double precision, 8 scalars)
// ---------------------------------------------------------------------------
__global__ void k_margin() {
  int b = threadIdx.x;
  if (b >= BATCH) return;
  const double N = (double)NPB;
  double s = g_bsum[b], s2 = g_bsumsq[b];
  double mean = s / N;
  double var  = (s2 - s*s/N) / (N - 1.0);   // unbiased (ddof=1)
  double sd   = sqrt(fabs(var));
  double z    = -mean / sd;
  double cdf  = 0.5 * (1.0 + erf(z * 0.70710678118654752440));
  double safe = fmax(cdf, 1e-30);
  double ma   = -sd * exp(-(mean/sd)*(mean/sd)*0.5)
                / 2.50662827463100050241 / safe + mean;
  double m    = (cdf > 0.001) ? ma : (-3.0 * sd);
  g_margin[b] = (float)m;
}

// ---------------------------------------------------------------------------
// K_C: zt[b,l] = sum_c exp(max(xt[b,c,l], margin[b])). Same layout as K_A.
// ---------------------------------------------------------------------------
__global__ void __launch_bounds__(256) k_C(const float* __restrict__ xt) {
  int bid = blockIdx.x;
  int cc = bid & 15;
  int lt = (bid >> 4) & 3;
  int b  = bid >> 6;
  int t  = threadIdx.x;
  int l  = lt * 1024 + t * 4;
  float m = g_margin[b];

  size_t base = (size_t)b * NPB + (size_t)(cc * 64) * LL + l;
  const float4* pt = reinterpret_cast<const float4*>(xt + base);

  float z0 = 0.f, z1 = 0.f, z2 = 0.f, z3 = 0.f;
#pragma unroll 8
  for (int c = 0; c < 64; c++) {
    float4 w = pt[(size_t)c * (LL/4)];
    z0 += __expf(fmaxf(w.x, m)); z1 += __expf(fmaxf(w.y, m));
    z2 += __expf(fmaxf(w.z, m)); z3 += __expf(fmaxf(w.w, m));
  }
  float* zp = &g_zt[b * LL + l];
  atomicAdd(zp + 0, z0); atomicAdd(zp + 1, z1);
  atomicAdd(zp + 2, z2); atomicAdd(zp + 3, z3);
}

// ---------------------------------------------------------------------------
// K_tab: g_zs <- 1/zs, g_zt <- log(zt). 32K elements, in place.
// ---------------------------------------------------------------------------
__global__ void __launch_bounds__(256) k_tab() {
  int i = blockIdx.x * 256 + threadIdx.x;
  g_zs[i] = 1.0f / g_zs[i];
  g_zt[i] = logf(g_zt[i]);
}

// ---------------------------------------------------------------------------
// K_D: elementwise entropy + writeout + loss.
//   e = exp(xs) * invzs * (max(xt, margin) - lzt)
// Grid: 1024 blocks = 8 b x 4 l-tiles(1024) x 32 c-chunks(32). Thread owns 4 l,
// table values (invzs, lzt) held in registers across the whole c-loop.
// Output stores are scalar (d_out+1 is only 4B-aligned).
// ---------------------------------------------------------------------------
__global__ void __launch_bounds__(256) k_D(const float* __restrict__ xs,
                                           const float* __restrict__ xt,
                                           float* __restrict__ eout) {
  int bid = blockIdx.x;
  int cc = bid & 31;
  int lt = (bid >> 5) & 3;
  int b  = bid >> 7;
  int t  = threadIdx.x;
  int l  = lt * 1024 + t * 4;

  float4 iz = *reinterpret_cast<const float4*>(&g_zs[b * LL + l]);
  float4 lz = *reinterpret_cast<const float4*>(&g_zt[b * LL + l]);
  float m = g_margin[b];

  size_t base = (size_t)b * NPB + (size_t)(cc * 32) * LL + l;
  const float4* ps = reinterpret_cast<const float4*>(xs + base);
  const float4* pt = reinterpret_cast<const float4*>(xt + base);
  float* po = eout + base;

  float acc = 0.f;
#pragma unroll 4
  for (int c = 0; c < 32; c++) {
    float4 a = ps[(size_t)c * (LL/4)];
    float4 w = pt[(size_t)c * (LL/4)];
    float e0 = __expf(a.x) * iz.x * (fmaxf(w.x, m) - lz.x);
    float e1 = __expf(a.y) * iz.y * (fmaxf(w.y, m) - lz.y);
    float e2 = __expf(a.z) * iz.z * (fmaxf(w.z, m) - lz.z);
    float e3 = __expf(a.w) * iz.w * (fmaxf(w.w, m) - lz.w);
    float* d = po + (size_t)c * LL;
    d[0] = e0; d[1] = e1; d[2] = e2; d[3] = e3;
    acc += (e0 + e1) + (e2 + e3);
  }

#pragma unroll
  for (int o = 16; o; o >>= 1) acc += __shfl_xor_sync(0xffffffffu, acc, o);
  __shared__ float wacc[8];
  int warp = t >> 5, lane = t & 31;
  if (lane == 0) wacc[warp] = acc;
  __syncthreads();
  if (t == 0) {
    float ts = 0.f;
#pragma unroll
    for (int w = 0; w < 8; w++) ts += wacc[w];
    atomicAdd(&g_loss, (double)ts);
  }
}

// ---------------------------------------------------------------------------
// K_loss: loss = -total / (B*L)
// ---------------------------------------------------------------------------
__global__ void k_loss(float* __restrict__ out0) {
  if (threadIdx.x == 0) out0[0] = (float)(-g_loss / (double)(BATCH * LL));
}

// ---------------------------------------------------------------------------
extern "C" void kernel_launch(void* const* d_in, const int* in_sizes, int n_in,
                              void* d_out, int out_size) {
  // metadata order: x_s, x_t, x_ts, x_st, i
  const float* xs = (const float*)d_in[2];  // x_ts -> source
  const float* xt = (const float*)d_in[3];  // x_st -> target (margin source)
  float* out = (float*)d_out;               // [0] = loss, [1..] = entropy [B,C,L]

  k_zero  <<<NBL/256, 256>>>();
  k_A     <<<512, 256>>>(xs, xt);
  k_margin<<<1, 32>>>();
  k_C     <<<512, 256>>>(xt);
  k_tab   <<<NBL/256, 256>>>();
  k_D     <<<1024, 256>>>(xs, xt, out + 1);
  k_loss  <<<1, 32>>>(out);
}